// round 2
// baseline (speedup 1.0000x reference)
#include <cuda_runtime.h>
#include <cuda_bf16.h>
#include <cstdint>

// ============================================================================
// NT-Xent loss, GB300 (sm_103a) -- portable HMMA (mma.sync bf16) version.
// tcgen05 is rejected by the harness's compute_103 PTX pass, so we use
// mma.sync.m16n8k16 with ldmatrix-staged smem tiles.
//
// loss = (1/N) sum_r [ log( sum_k e^{G[r][k]} - e^{G[r][(r+half)%N]} ) - G[r][r] ]
// where G[r][k] = (zn[r].zn[k]) / 0.5, zn = row-normalized cat(z_i, z_j).
// All logits bounded in [-2,2] -> plain exp-sum, no online max needed.
// ============================================================================

#define N_TOTAL 8192
#define HALF    4096
#define DIM     128
#define TWO_LOG2E 2.8853900817779268f   // 2 * log2(e)
#define LOG2E     1.4426950408889634f

__device__ __nv_bfloat16 g_znb[N_TOTAL * DIM];
__device__ float g_rowsum[N_TOTAL];
__device__ float g_pos[N_TOTAL];
__device__ float g_exc[N_TOTAL];

__device__ __forceinline__ uint32_t smem_to_u32(const void* p) {
    uint32_t a;
    asm("{ .reg .u64 t; cvta.to.shared.u64 t, %1; cvt.u32.u64 %0, t; }"
        : "=r"(a) : "l"(p));
    return a;
}

__device__ __forceinline__ float ex2_approx(float x) {
    float y;
    asm("ex2.approx.f32 %0, %1;" : "=f"(y) : "f"(x));
    return y;
}

// ============================================================================
// Kernel 0: zero row sums
// ============================================================================
__global__ void zero_kernel() {
    int i = blockIdx.x * blockDim.x + threadIdx.x;
    if (i < N_TOTAL) g_rowsum[i] = 0.0f;
}

// ============================================================================
// Kernel 1: normalize rows -> bf16 (one warp per row)
// ============================================================================
__global__ void normalize_kernel(const float* __restrict__ zi,
                                 const float* __restrict__ zj) {
    int row  = blockIdx.x * 8 + (threadIdx.x >> 5);
    int lane = threadIdx.x & 31;
    const float* src = (row < HALF) ? (zi + (size_t)row * DIM)
                                    : (zj + (size_t)(row - HALF) * DIM);
    float4 v = reinterpret_cast<const float4*>(src)[lane];
    float ss = v.x * v.x + v.y * v.y + v.z * v.z + v.w * v.w;
    #pragma unroll
    for (int o = 16; o; o >>= 1) ss += __shfl_xor_sync(0xFFFFFFFFu, ss, o);
    float inv = 1.0f / fmaxf(sqrtf(ss), 1e-8f);
    __nv_bfloat162* dst =
        reinterpret_cast<__nv_bfloat162*>(g_znb + (size_t)row * DIM + lane * 4);
    dst[0] = __floats2bfloat162_rn(v.x * inv, v.y * inv);
    dst[1] = __floats2bfloat162_rn(v.z * inv, v.w * inv);
}

// ============================================================================
// Kernel 2: per-row pos / excluded logits (one warp per row)
// ============================================================================
__global__ void pairdots_kernel() {
    int row  = blockIdx.x * 8 + (threadIdx.x >> 5);
    int lane = threadIdx.x & 31;
    int row2 = (row + HALF) & (N_TOTAL - 1);
    const __nv_bfloat162* a =
        reinterpret_cast<const __nv_bfloat162*>(g_znb + (size_t)row * DIM) + lane * 2;
    const __nv_bfloat162* b =
        reinterpret_cast<const __nv_bfloat162*>(g_znb + (size_t)row2 * DIM) + lane * 2;
    float2 a0 = __bfloat1622float2(a[0]);
    float2 a1 = __bfloat1622float2(a[1]);
    float2 b0 = __bfloat1622float2(b[0]);
    float2 b1 = __bfloat1622float2(b[1]);
    float dp = a0.x * a0.x + a0.y * a0.y + a1.x * a1.x + a1.y * a1.y;
    float de = a0.x * b0.x + a0.y * b0.y + a1.x * b1.x + a1.y * b1.y;
    #pragma unroll
    for (int o = 16; o; o >>= 1) {
        dp += __shfl_xor_sync(0xFFFFFFFFu, dp, o);
        de += __shfl_xor_sync(0xFFFFFFFFu, de, o);
    }
    if (lane == 0) {
        g_pos[row] = 2.0f * dp;
        g_exc[row] = 2.0f * de;
    }
}

// ============================================================================
// Kernel 3: Gram GEMM (128x128 tile per CTA, HMMA) + fused exp-sum epilogue
//
// smem layout (dynamic):
//   A tile: 128 rows x 256B (bf16 x 128), 16B-chunk XOR swizzle  -> 32 KB
//   B tile: same                                                  -> 32 KB
//   rowsum: 128 floats                                            -> 512 B
// ============================================================================
#define SMEM_A   0
#define SMEM_B   32768
#define SMEM_RS  65536
#define SMEM_TOT (65536 + 512)

// swizzled byte offset within a tile: row-major 256B rows, 16B chunk XOR row&7
__device__ __forceinline__ uint32_t tile_off(int row, int chunk16) {
    return (uint32_t)(row * 256 + ((chunk16 ^ (row & 7)) << 4));
}

__global__ void __launch_bounds__(256, 2)
gram_kernel() {
    extern __shared__ char smem[];
    uint32_t sb = smem_to_u32(smem);
    const int tid  = threadIdx.x;
    const int wid  = tid >> 5;
    const int lane = tid & 31;

    const int m0 = (blockIdx.x >> 6) << 7;   // 64 m-tiles of 128
    const int n0 = (blockIdx.x & 63) << 7;   // 64 n-tiles of 128

    // zero smem row sums
    float* srow = reinterpret_cast<float*>(smem + SMEM_RS);
    if (tid < 128) srow[tid] = 0.0f;

    // ---- load A and B tiles (each 2048 uint4), swizzled ----
    {
        const uint4* gA = reinterpret_cast<const uint4*>(g_znb + (size_t)m0 * DIM);
        const uint4* gB = reinterpret_cast<const uint4*>(g_znb + (size_t)n0 * DIM);
        #pragma unroll
        for (int it = 0; it < 8; it++) {
            int idx = tid + it * 256;
            int row = idx >> 4, c = idx & 15;
            uint32_t off = tile_off(row, c);
            *reinterpret_cast<uint4*>(smem + SMEM_A + off) = gA[(row << 4) + c];
            *reinterpret_cast<uint4*>(smem + SMEM_B + off) = gB[(row << 4) + c];
        }
    }
    __syncthreads();

    // ---- warp tiling: 4 m-strips x 2 n-strips; warp tile 32(m) x 64(n) ----
    const int wm = (wid & 3) * 32;
    const int wn = (wid >> 2) * 64;

    float c[2][8][4];
    #pragma unroll
    for (int mt = 0; mt < 2; mt++)
        #pragma unroll
        for (int nt = 0; nt < 8; nt++)
            #pragma unroll
            for (int q = 0; q < 4; q++) c[mt][nt][q] = 0.0f;

    const int l7 = lane & 7;
    const int g  = lane >> 3;   // 0..3

    #pragma unroll
    for (int ks = 0; ks < 8; ks++) {
        // A fragments: 2 m16 tiles
        uint32_t a[2][4];
        #pragma unroll
        for (int mt = 0; mt < 2; mt++) {
            int row = wm + mt * 16 + l7 + ((g & 1) << 3);
            int ch  = ks * 2 + (g >> 1);
            uint32_t addr = sb + SMEM_A + tile_off(row, ch);
            asm volatile(
                "ldmatrix.sync.aligned.m8n8.x4.shared.b16 {%0,%1,%2,%3}, [%4];"
                : "=r"(a[mt][0]), "=r"(a[mt][1]), "=r"(a[mt][2]), "=r"(a[mt][3])
                : "r"(addr));
        }
        // B fragments: 4 n16 loads -> 8 n8 frags
        uint32_t b[8][2];
        #pragma unroll
        for (int nt2 = 0; nt2 < 4; nt2++) {
            int row = wn + nt2 * 16 + l7 + ((g >> 1) << 3);
            int ch  = ks * 2 + (g & 1);
            uint32_t addr = sb + SMEM_B + tile_off(row, ch);
            asm volatile(
                "ldmatrix.sync.aligned.m8n8.x4.shared.b16 {%0,%1,%2,%3}, [%4];"
                : "=r"(b[nt2 * 2][0]),     "=r"(b[nt2 * 2][1]),
                  "=r"(b[nt2 * 2 + 1][0]), "=r"(b[nt2 * 2 + 1][1])
                : "r"(addr));
        }
        // 16 MMAs
        #pragma unroll
        for (int mt = 0; mt < 2; mt++)
            #pragma unroll
            for (int nt = 0; nt < 8; nt++)
                asm volatile(
                    "mma.sync.aligned.m16n8k16.row.col.f32.bf16.bf16.f32 "
                    "{%0,%1,%2,%3}, {%4,%5,%6,%7}, {%8,%9}, {%0,%1,%2,%3};"
                    : "+f"(c[mt][nt][0]), "+f"(c[mt][nt][1]),
                      "+f"(c[mt][nt][2]), "+f"(c[mt][nt][3])
                    : "r"(a[mt][0]), "r"(a[mt][1]), "r"(a[mt][2]), "r"(a[mt][3]),
                      "r"(b[nt][0]), "r"(b[nt][1]));
    }

    // ---- epilogue: exp2(acc * 2log2e), reduce to per-row sums ----
    #pragma unroll
    for (int mt = 0; mt < 2; mt++) {
        float s0 = 0.0f, s1 = 0.0f;
        #pragma unroll
        for (int nt = 0; nt < 8; nt++) {
            s0 += ex2_approx(c[mt][nt][0] * TWO_LOG2E)
                + ex2_approx(c[mt][nt][1] * TWO_LOG2E);
            s1 += ex2_approx(c[mt][nt][2] * TWO_LOG2E)
                + ex2_approx(c[mt][nt][3] * TWO_LOG2E);
        }
        // quad reduce (lanes sharing the same row: xor 1, 2)
        s0 += __shfl_xor_sync(0xFFFFFFFFu, s0, 1);
        s0 += __shfl_xor_sync(0xFFFFFFFFu, s0, 2);
        s1 += __shfl_xor_sync(0xFFFFFFFFu, s1, 1);
        s1 += __shfl_xor_sync(0xFFFFFFFFu, s1, 2);
        if ((lane & 3) == 0) {
            int r = wm + mt * 16 + (lane >> 2);
            atomicAdd(&srow[r],     s0);
            atomicAdd(&srow[r + 8], s1);
        }
    }
    __syncthreads();
    if (tid < 128) atomicAdd(&g_rowsum[m0 + tid], srow[tid]);
}

// ============================================================================
// Kernel 4: finalize -> scalar loss
// ============================================================================
__global__ void finalize_kernel(float* __restrict__ out) {
    __shared__ float red[256];
    float acc = 0.0f;
    for (int r = threadIdx.x; r < N_TOTAL; r += 256) {
        float S = g_rowsum[r] - ex2_approx(g_exc[r] * LOG2E);
        acc += logf(S) - g_pos[r];
    }
    red[threadIdx.x] = acc;
    __syncthreads();
    #pragma unroll
    for (int s = 128; s > 0; s >>= 1) {
        if (threadIdx.x < s) red[threadIdx.x] += red[threadIdx.x + s];
        __syncthreads();
    }
    if (threadIdx.x == 0) out[0] = red[0] / (float)N_TOTAL;
}

// ============================================================================
// launch
// ============================================================================
extern "C" void kernel_launch(void* const* d_in, const int* in_sizes, int n_in,
                              void* d_out, int out_size) {
    (void)in_sizes; (void)n_in; (void)out_size;
    const float* zi = (const float*)d_in[0];
    const float* zj = (const float*)d_in[1];
    float* out = (float*)d_out;

    zero_kernel<<<8, 1024>>>();
    normalize_kernel<<<N_TOTAL / 8, 256>>>(zi, zj);
    pairdots_kernel<<<N_TOTAL / 8, 256>>>();

    cudaFuncSetAttribute(gram_kernel,
                         cudaFuncAttributeMaxDynamicSharedMemorySize, SMEM_TOT);
    gram_kernel<<<4096, 256, SMEM_TOT>>>();

    finalize_kernel<<<1, 256>>>(out);
}

// round 3
// speedup vs baseline: 1.3237x; 1.3237x over previous
#include <cuda_runtime.h>
#include <cuda_bf16.h>
#include <cstdint>

// ============================================================================
// NT-Xent loss, GB300 (sm_103a) -- HMMA (mma.sync bf16), symmetric-Gram version.
// Only upper-triangular 128x128 tiles computed (2080 CTAs instead of 4096);
// off-diagonal tiles contribute exp-sums to BOTH row blocks (row + col
// reductions). pos (diag of G) and exc (G[r][r+half]) are extracted in the
// GEMM epilogue, eliminating the separate pairdots kernel.
// ============================================================================

#define N_TOTAL 8192
#define HALF    4096
#define DIM     128
#define TWO_LOG2E 2.8853900817779268f   // 2 * log2(e)
#define LOG2E     1.4426950408889634f

__device__ __nv_bfloat16 g_znb[N_TOTAL * DIM];
__device__ float g_rowsum[N_TOTAL];
__device__ float g_pos[N_TOTAL];
__device__ float g_exc[N_TOTAL];

__device__ __forceinline__ uint32_t smem_to_u32(const void* p) {
    uint32_t a;
    asm("{ .reg .u64 t; cvta.to.shared.u64 t, %1; cvt.u32.u64 %0, t; }"
        : "=r"(a) : "l"(p));
    return a;
}

__device__ __forceinline__ float ex2_approx(float x) {
    float y;
    asm("ex2.approx.f32 %0, %1;" : "=f"(y) : "f"(x));
    return y;
}

// ============================================================================
// Kernel 1: normalize rows -> bf16 (one warp per row) + zero rowsums
// ============================================================================
__global__ void normalize_kernel(const float* __restrict__ zi,
                                 const float* __restrict__ zj) {
    int row  = blockIdx.x * 8 + (threadIdx.x >> 5);
    int lane = threadIdx.x & 31;
    const float* src = (row < HALF) ? (zi + (size_t)row * DIM)
                                    : (zj + (size_t)(row - HALF) * DIM);
    float4 v = reinterpret_cast<const float4*>(src)[lane];
    float ss = v.x * v.x + v.y * v.y + v.z * v.z + v.w * v.w;
    #pragma unroll
    for (int o = 16; o; o >>= 1) ss += __shfl_xor_sync(0xFFFFFFFFu, ss, o);
    float inv = 1.0f / fmaxf(sqrtf(ss), 1e-8f);
    __nv_bfloat162* dst =
        reinterpret_cast<__nv_bfloat162*>(g_znb + (size_t)row * DIM + lane * 4);
    dst[0] = __floats2bfloat162_rn(v.x * inv, v.y * inv);
    dst[1] = __floats2bfloat162_rn(v.z * inv, v.w * inv);
    if (lane == 0) g_rowsum[row] = 0.0f;
}

// ============================================================================
// Kernel 2: symmetric Gram GEMM + fused exp-sum epilogue
// smem: A tile 32KB | B tile 32KB | srow 128f | scol 128f
// ============================================================================
#define SMEM_A   0
#define SMEM_B   32768
#define SMEM_RS  65536
#define SMEM_TOT (65536 + 1024)

__device__ __forceinline__ uint32_t tile_off(int row, int chunk16) {
    return (uint32_t)(row * 256 + ((chunk16 ^ (row & 7)) << 4));
}

__global__ void __launch_bounds__(256, 2)
gram_kernel() {
    extern __shared__ char smem[];
    uint32_t sb = smem_to_u32(smem);
    const int tid  = threadIdx.x;
    const int wid  = tid >> 5;
    const int lane = tid & 31;

    // ---- map blockIdx -> (mi, ni), mi <= ni over 64x64 tile grid ----
    int mi, ni;
    {
        int bid = blockIdx.x;
        if (bid < 64) { mi = bid; ni = bid; }
        else {
            int idx = bid - 64;
            mi = 0;
            int rowlen = 63;
            while (idx >= rowlen) { idx -= rowlen; rowlen--; mi++; }
            ni = mi + 1 + idx;
        }
    }
    const bool diag = (mi == ni);
    const int m0 = mi << 7;
    const int n0 = ni << 7;

    float* srow = reinterpret_cast<float*>(smem + SMEM_RS);
    float* scol = srow + 128;
    if (tid < 128) { srow[tid] = 0.0f; scol[tid] = 0.0f; }

    // ---- load A (rows m0..) and B (rows n0..) tiles, swizzled ----
    {
        const uint4* gA = reinterpret_cast<const uint4*>(g_znb + (size_t)m0 * DIM);
        const uint4* gB = reinterpret_cast<const uint4*>(g_znb + (size_t)n0 * DIM);
        #pragma unroll
        for (int it = 0; it < 8; it++) {
            int idx = tid + it * 256;
            int row = idx >> 4, ch = idx & 15;
            uint32_t off = tile_off(row, ch);
            *reinterpret_cast<uint4*>(smem + SMEM_A + off) = gA[(row << 4) + ch];
            *reinterpret_cast<uint4*>(smem + SMEM_B + off) = gB[(row << 4) + ch];
        }
    }
    __syncthreads();

    // ---- warp tiling: 4 m-strips x 2 n-strips; warp tile 32(m) x 64(n) ----
    const int wm = (wid & 3) * 32;
    const int wn = (wid >> 2) * 64;

    float c[2][8][4];
    #pragma unroll
    for (int mt = 0; mt < 2; mt++)
        #pragma unroll
        for (int nt = 0; nt < 8; nt++)
            #pragma unroll
            for (int q = 0; q < 4; q++) c[mt][nt][q] = 0.0f;

    const int l7 = lane & 7;
    const int g  = lane >> 3;   // 0..3

    #pragma unroll
    for (int ks = 0; ks < 8; ks++) {
        uint32_t a[2][4];
        #pragma unroll
        for (int mt = 0; mt < 2; mt++) {
            int row = wm + mt * 16 + l7 + ((g & 1) << 3);
            int ch  = ks * 2 + (g >> 1);
            uint32_t addr = sb + SMEM_A + tile_off(row, ch);
            asm volatile(
                "ldmatrix.sync.aligned.m8n8.x4.shared.b16 {%0,%1,%2,%3}, [%4];"
                : "=r"(a[mt][0]), "=r"(a[mt][1]), "=r"(a[mt][2]), "=r"(a[mt][3])
                : "r"(addr));
        }
        uint32_t b[8][2];
        #pragma unroll
        for (int nt2 = 0; nt2 < 4; nt2++) {
            int row = wn + nt2 * 16 + l7 + ((g >> 1) << 3);
            int ch  = ks * 2 + (g & 1);
            uint32_t addr = sb + SMEM_B + tile_off(row, ch);
            asm volatile(
                "ldmatrix.sync.aligned.m8n8.x4.shared.b16 {%0,%1,%2,%3}, [%4];"
                : "=r"(b[nt2 * 2][0]),     "=r"(b[nt2 * 2][1]),
                  "=r"(b[nt2 * 2 + 1][0]), "=r"(b[nt2 * 2 + 1][1])
                : "r"(addr));
        }
        #pragma unroll
        for (int mt = 0; mt < 2; mt++)
            #pragma unroll
            for (int nt = 0; nt < 8; nt++)
                asm volatile(
                    "mma.sync.aligned.m16n8k16.row.col.f32.bf16.bf16.f32 "
                    "{%0,%1,%2,%3}, {%4,%5,%6,%7}, {%8,%9}, {%0,%1,%2,%3};"
                    : "+f"(c[mt][nt][0]), "+f"(c[mt][nt][1]),
                      "+f"(c[mt][nt][2]), "+f"(c[mt][nt][3])
                    : "r"(a[mt][0]), "r"(a[mt][1]), "r"(a[mt][2]), "r"(a[mt][3]),
                      "r"(b[nt][0]), "r"(b[nt][1]));
    }

    // ---- extraction: pos on diagonal tiles, exc on (ni-mi==32) tiles ----
    // fragment element (mt,nt,q): local row = wm+mt*16+(lane>>2)+((q&2)<<2)
    //                             local col = wn+nt*8+((lane&3)<<1)+(q&1)
    if (diag) {
        #pragma unroll
        for (int mt = 0; mt < 2; mt++)
            #pragma unroll
            for (int nt = 0; nt < 8; nt++)
                #pragma unroll
                for (int q = 0; q < 4; q++) {
                    int r_loc = wm + mt * 16 + (lane >> 2) + ((q & 2) << 2);
                    int c_loc = wn + nt * 8 + ((lane & 3) << 1) + (q & 1);
                    if (r_loc == c_loc)
                        g_pos[m0 + r_loc] = 2.0f * c[mt][nt][q];
                }
    } else if (ni - mi == (HALF >> 7)) {
        #pragma unroll
        for (int mt = 0; mt < 2; mt++)
            #pragma unroll
            for (int nt = 0; nt < 8; nt++)
                #pragma unroll
                for (int q = 0; q < 4; q++) {
                    int r_loc = wm + mt * 16 + (lane >> 2) + ((q & 2) << 2);
                    int c_loc = wn + nt * 8 + ((lane & 3) << 1) + (q & 1);
                    if (r_loc == c_loc) {
                        float v = 2.0f * c[mt][nt][q];
                        g_exc[m0 + r_loc] = v;
                        g_exc[n0 + r_loc] = v;
                    }
                }
    }

    // ---- epilogue: exps once; row sums always, col sums if off-diagonal ----
    float cs0[8], cs1[8];
    #pragma unroll
    for (int nt = 0; nt < 8; nt++) { cs0[nt] = 0.0f; cs1[nt] = 0.0f; }

    #pragma unroll
    for (int mt = 0; mt < 2; mt++) {
        float s0 = 0.0f, s1 = 0.0f;
        #pragma unroll
        for (int nt = 0; nt < 8; nt++) {
            float e0 = ex2_approx(c[mt][nt][0] * TWO_LOG2E);
            float e1 = ex2_approx(c[mt][nt][1] * TWO_LOG2E);
            float e2 = ex2_approx(c[mt][nt][2] * TWO_LOG2E);
            float e3 = ex2_approx(c[mt][nt][3] * TWO_LOG2E);
            s0 += e0 + e1;
            s1 += e2 + e3;
            cs0[nt] += e0 + e2;   // col 2j
            cs1[nt] += e1 + e3;   // col 2j+1
        }
        s0 += __shfl_xor_sync(0xFFFFFFFFu, s0, 1);
        s0 += __shfl_xor_sync(0xFFFFFFFFu, s0, 2);
        s1 += __shfl_xor_sync(0xFFFFFFFFu, s1, 1);
        s1 += __shfl_xor_sync(0xFFFFFFFFu, s1, 2);
        if ((lane & 3) == 0) {
            int r = wm + mt * 16 + (lane >> 2);
            atomicAdd(&srow[r],     s0);
            atomicAdd(&srow[r + 8], s1);
        }
    }

    if (!diag) {
        #pragma unroll
        for (int nt = 0; nt < 8; nt++) {
            float u = cs0[nt], v = cs1[nt];
            u += __shfl_xor_sync(0xFFFFFFFFu, u, 4);
            u += __shfl_xor_sync(0xFFFFFFFFu, u, 8);
            u += __shfl_xor_sync(0xFFFFFFFFu, u, 16);
            v += __shfl_xor_sync(0xFFFFFFFFu, v, 4);
            v += __shfl_xor_sync(0xFFFFFFFFu, v, 8);
            v += __shfl_xor_sync(0xFFFFFFFFu, v, 16);
            if (lane < 4) {
                int cix = wn + nt * 8 + (lane << 1);
                atomicAdd(&scol[cix],     u);
                atomicAdd(&scol[cix + 1], v);
            }
        }
    }

    __syncthreads();
    if (tid < 128) {
        atomicAdd(&g_rowsum[m0 + tid], srow[tid]);
        if (!diag) atomicAdd(&g_rowsum[n0 + tid], scol[tid]);
    }
}

// ============================================================================
// Kernel 3: finalize -> scalar loss
// ============================================================================
__global__ void finalize_kernel(float* __restrict__ out) {
    __shared__ float red[256];
    float acc = 0.0f;
    for (int r = threadIdx.x; r < N_TOTAL; r += 256) {
        float S = g_rowsum[r] - ex2_approx(g_exc[r] * LOG2E);
        acc += logf(S) - g_pos[r];
    }
    red[threadIdx.x] = acc;
    __syncthreads();
    #pragma unroll
    for (int s = 128; s > 0; s >>= 1) {
        if (threadIdx.x < s) red[threadIdx.x] += red[threadIdx.x + s];
        __syncthreads();
    }
    if (threadIdx.x == 0) out[0] = red[0] / (float)N_TOTAL;
}

// ============================================================================
// launch
// ============================================================================
extern "C" void kernel_launch(void* const* d_in, const int* in_sizes, int n_in,
                              void* d_out, int out_size) {
    (void)in_sizes; (void)n_in; (void)out_size;
    const float* zi = (const float*)d_in[0];
    const float* zj = (const float*)d_in[1];
    float* out = (float*)d_out;

    normalize_kernel<<<N_TOTAL / 8, 256>>>(zi, zj);

    cudaFuncSetAttribute(gram_kernel,
                         cudaFuncAttributeMaxDynamicSharedMemorySize, SMEM_TOT);
    gram_kernel<<<64 + (64 * 63) / 2, 256, SMEM_TOT>>>();

    finalize_kernel<<<1, 256>>>(out);
}

// round 4
// speedup vs baseline: 2.0877x; 1.5771x over previous
#include <cuda_runtime.h>
#include <cuda_bf16.h>
#include <cstdint>

// ============================================================================
// NT-Xent loss, GB300 (sm_103a) -- HMMA symmetric-Gram, persistent CTAs +
// cp.async double-buffered B tiles, A reused along tile rows.
// ============================================================================

#define N_TOTAL 8192
#define HALF    4096
#define DIM     128
#define TWO_LOG2E 2.8853900817779268f
#define LOG2E     1.4426950408889634f

#define GRID_GRAM 296         // 148 SMs * 2 CTAs
#define TILES_TOT 2080        // 64 diag + 2016 upper

__device__ __nv_bfloat16 g_znb[N_TOTAL * DIM];
__device__ float g_rowsum[N_TOTAL];
__device__ float g_pos[N_TOTAL];
__device__ float g_exc[N_TOTAL];
__device__ float g_acc;
__device__ unsigned int g_cnt;

__device__ __forceinline__ uint32_t smem_to_u32(const void* p) {
    uint32_t a;
    asm("{ .reg .u64 t; cvta.to.shared.u64 t, %1; cvt.u32.u64 %0, t; }"
        : "=r"(a) : "l"(p));
    return a;
}
__device__ __forceinline__ float ex2_approx(float x) {
    float y;
    asm("ex2.approx.f32 %0, %1;" : "=f"(y) : "f"(x));
    return y;
}

// ============================================================================
// Kernel 1: normalize rows -> bf16 (warp per row) + zero accumulators
// ============================================================================
__global__ void normalize_kernel(const float* __restrict__ zi,
                                 const float* __restrict__ zj) {
    int row  = blockIdx.x * 8 + (threadIdx.x >> 5);
    int lane = threadIdx.x & 31;
    const float* src = (row < HALF) ? (zi + (size_t)row * DIM)
                                    : (zj + (size_t)(row - HALF) * DIM);
    float4 v = reinterpret_cast<const float4*>(src)[lane];
    float ss = v.x * v.x + v.y * v.y + v.z * v.z + v.w * v.w;
    #pragma unroll
    for (int o = 16; o; o >>= 1) ss += __shfl_xor_sync(0xFFFFFFFFu, ss, o);
    float inv = 1.0f / fmaxf(sqrtf(ss), 1e-8f);
    __nv_bfloat162* dst =
        reinterpret_cast<__nv_bfloat162*>(g_znb + (size_t)row * DIM + lane * 4);
    dst[0] = __floats2bfloat162_rn(v.x * inv, v.y * inv);
    dst[1] = __floats2bfloat162_rn(v.z * inv, v.w * inv);
    if (lane == 0) g_rowsum[row] = 0.0f;
    if (row == 0 && lane == 0) { g_acc = 0.0f; g_cnt = 0u; }
}

// ============================================================================
// Kernel 2: persistent symmetric Gram GEMM + fused exp-sum epilogue
// smem: A 32KB | B0 32KB | B1 32KB
// ============================================================================
#define SMEM_A   0
#define SMEM_B0  32768
#define SMEM_TOT 98304

__device__ __forceinline__ uint32_t tile_off(int row, int chunk16) {
    return (uint32_t)(row * 256 + ((chunk16 ^ (row & 7)) << 4));
}

__device__ __forceinline__ void load_tile_async(uint32_t sdst, int row0, int tid) {
    const uint4* gp = reinterpret_cast<const uint4*>(g_znb + (size_t)row0 * DIM);
    #pragma unroll
    for (int it = 0; it < 8; it++) {
        int idx = tid + it * 256;
        int row = idx >> 4, ch = idx & 15;
        asm volatile("cp.async.cg.shared.global [%0], [%1], 16;"
            :: "r"(sdst + tile_off(row, ch)), "l"(gp + (row << 4) + ch));
    }
}
#define CP_COMMIT() asm volatile("cp.async.commit_group;" ::: "memory")
#define CP_WAIT0()  asm volatile("cp.async.wait_group 0;"  ::: "memory")

__global__ void __launch_bounds__(256, 2)
gram_kernel() {
    extern __shared__ char smem[];
    uint32_t sb = smem_to_u32(smem);
    const int tid  = threadIdx.x;
    const int wid  = tid >> 5;
    const int lane = tid & 31;
    const int bid  = blockIdx.x;

    // contiguous chunk of linear upper-tri tile indices
    const int start = bid * 7 + (bid < 8 ? bid : 8);
    const int count = (bid < 8) ? 8 : 7;

    // linear index -> (mi, ni), row-major upper triangle incl. diagonal
    int mi = 0, rem = start, len = 64;
    while (rem >= len) { rem -= len; len--; mi++; }
    int ni = mi + rem;

    const int wm = (wid & 3) * 32;
    const int wn = (wid >> 2) * 64;
    const int l7 = lane & 7;
    const int g  = lane >> 3;

    // initial fill: A(mi), B0(ni)
    load_tile_async(sb + SMEM_A, mi << 7, tid);
    load_tile_async(sb + SMEM_B0, ni << 7, tid);
    CP_COMMIT();
    CP_WAIT0();
    __syncthreads();
    int cur = 0;

    for (int i = 0; i < count; i++) {
        const int m0 = mi << 7, n0 = ni << 7;
        const bool diag = (mi == ni);
        const bool last = (i == count - 1);
        int mi_n = mi, ni_n = ni + 1;
        if (ni_n == 64) { mi_n = mi + 1; ni_n = mi_n; }
        const bool pf = !last && (mi_n == mi);
        if (pf) {
            load_tile_async(sb + SMEM_B0 + ((1 - cur) << 15), ni_n << 7, tid);
            CP_COMMIT();
        }
        const uint32_t bbase = sb + SMEM_B0 + (cur << 15);

        // ---- MMA mainloop ----
        float c[2][8][4];
        #pragma unroll
        for (int mt = 0; mt < 2; mt++)
            #pragma unroll
            for (int nt = 0; nt < 8; nt++)
                #pragma unroll
                for (int q = 0; q < 4; q++) c[mt][nt][q] = 0.0f;

        #pragma unroll
        for (int ks = 0; ks < 8; ks++) {
            uint32_t a[2][4];
            #pragma unroll
            for (int mt = 0; mt < 2; mt++) {
                int row = wm + mt * 16 + l7 + ((g & 1) << 3);
                int ch  = ks * 2 + (g >> 1);
                uint32_t addr = sb + SMEM_A + tile_off(row, ch);
                asm volatile(
                    "ldmatrix.sync.aligned.m8n8.x4.shared.b16 {%0,%1,%2,%3}, [%4];"
                    : "=r"(a[mt][0]), "=r"(a[mt][1]), "=r"(a[mt][2]), "=r"(a[mt][3])
                    : "r"(addr));
            }
            uint32_t b[8][2];
            #pragma unroll
            for (int nt2 = 0; nt2 < 4; nt2++) {
                int row = wn + nt2 * 16 + l7 + ((g >> 1) << 3);
                int ch  = ks * 2 + (g & 1);
                uint32_t addr = bbase + tile_off(row, ch);
                asm volatile(
                    "ldmatrix.sync.aligned.m8n8.x4.shared.b16 {%0,%1,%2,%3}, [%4];"
                    : "=r"(b[nt2 * 2][0]),     "=r"(b[nt2 * 2][1]),
                      "=r"(b[nt2 * 2 + 1][0]), "=r"(b[nt2 * 2 + 1][1])
                    : "r"(addr));
            }
            #pragma unroll
            for (int mt = 0; mt < 2; mt++)
                #pragma unroll
                for (int nt = 0; nt < 8; nt++)
                    asm volatile(
                        "mma.sync.aligned.m16n8k16.row.col.f32.bf16.bf16.f32 "
                        "{%0,%1,%2,%3}, {%4,%5,%6,%7}, {%8,%9}, {%0,%1,%2,%3};"
                        : "+f"(c[mt][nt][0]), "+f"(c[mt][nt][1]),
                          "+f"(c[mt][nt][2]), "+f"(c[mt][nt][3])
                        : "r"(a[mt][0]), "r"(a[mt][1]), "r"(a[mt][2]), "r"(a[mt][3]),
                          "r"(b[nt][0]), "r"(b[nt][1]));
        }

        // ---- pos / exc extraction ----
        if (diag) {
            #pragma unroll
            for (int mt = 0; mt < 2; mt++)
                #pragma unroll
                for (int nt = 0; nt < 8; nt++)
                    #pragma unroll
                    for (int q = 0; q < 4; q++) {
                        int r_loc = wm + mt * 16 + (lane >> 2) + ((q & 2) << 2);
                        int c_loc = wn + nt * 8 + ((lane & 3) << 1) + (q & 1);
                        if (r_loc == c_loc)
                            g_pos[m0 + r_loc] = 2.0f * c[mt][nt][q];
                    }
        } else if (ni - mi == (HALF >> 7)) {
            #pragma unroll
            for (int mt = 0; mt < 2; mt++)
                #pragma unroll
                for (int nt = 0; nt < 8; nt++)
                    #pragma unroll
                    for (int q = 0; q < 4; q++) {
                        int r_loc = wm + mt * 16 + (lane >> 2) + ((q & 2) << 2);
                        int c_loc = wn + nt * 8 + ((lane & 3) << 1) + (q & 1);
                        if (r_loc == c_loc) {
                            float v = 2.0f * c[mt][nt][q];
                            g_exc[m0 + r_loc] = v;
                            g_exc[n0 + r_loc] = v;
                        }
                    }
        }

        // ---- epilogue: exps once; row sums always, col sums if off-diag ----
        float cs0[8], cs1[8];
        #pragma unroll
        for (int nt = 0; nt < 8; nt++) { cs0[nt] = 0.0f; cs1[nt] = 0.0f; }

        #pragma unroll
        for (int mt = 0; mt < 2; mt++) {
            float s0 = 0.0f, s1 = 0.0f;
            #pragma unroll
            for (int nt = 0; nt < 8; nt++) {
                float e0 = ex2_approx(c[mt][nt][0] * TWO_LOG2E);
                float e1 = ex2_approx(c[mt][nt][1] * TWO_LOG2E);
                float e2 = ex2_approx(c[mt][nt][2] * TWO_LOG2E);
                float e3 = ex2_approx(c[mt][nt][3] * TWO_LOG2E);
                s0 += e0 + e1;
                s1 += e2 + e3;
                cs0[nt] += e0 + e2;
                cs1[nt] += e1 + e3;
            }
            s0 += __shfl_xor_sync(0xFFFFFFFFu, s0, 1);
            s0 += __shfl_xor_sync(0xFFFFFFFFu, s0, 2);
            s1 += __shfl_xor_sync(0xFFFFFFFFu, s1, 1);
            s1 += __shfl_xor_sync(0xFFFFFFFFu, s1, 2);
            if ((lane & 3) == 0) {
                int r = m0 + wm + mt * 16 + (lane >> 2);
                atomicAdd(&g_rowsum[r],     s0);
                atomicAdd(&g_rowsum[r + 8], s1);
            }
        }

        if (!diag) {
            #pragma unroll
            for (int nt = 0; nt < 8; nt++) {
                float u = cs0[nt], v = cs1[nt];
                u += __shfl_xor_sync(0xFFFFFFFFu, u, 4);
                u += __shfl_xor_sync(0xFFFFFFFFu, u, 8);
                u += __shfl_xor_sync(0xFFFFFFFFu, u, 16);
                v += __shfl_xor_sync(0xFFFFFFFFu, v, 4);
                v += __shfl_xor_sync(0xFFFFFFFFu, v, 8);
                v += __shfl_xor_sync(0xFFFFFFFFu, v, 16);
                if (lane < 4) {
                    int cix = n0 + wn + nt * 8 + (lane << 1);
                    atomicAdd(&g_rowsum[cix],     u);
                    atomicAdd(&g_rowsum[cix + 1], v);
                }
            }
        }

        // ---- advance pipeline ----
        if (!last) {
            if (pf) {
                CP_WAIT0();
                __syncthreads();
                cur ^= 1;
            } else {
                __syncthreads();   // all warps done reading A and B[cur]
                load_tile_async(sb + SMEM_A, mi_n << 7, tid);
                load_tile_async(sb + SMEM_B0 + (cur << 15), ni_n << 7, tid);
                CP_COMMIT();
                CP_WAIT0();
                __syncthreads();
            }
            mi = mi_n; ni = ni_n;
        }
    }
}

// ============================================================================
// Kernel 3: finalize -> scalar loss (32 CTAs, last block writes)
// ============================================================================
__global__ void finalize_kernel(float* __restrict__ out) {
    __shared__ float red[256];
    int r = blockIdx.x * 256 + threadIdx.x;
    float S = g_rowsum[r] - ex2_approx(g_exc[r] * LOG2E);
    float acc = logf(S) - g_pos[r];
    red[threadIdx.x] = acc;
    __syncthreads();
    #pragma unroll
    for (int s = 128; s > 0; s >>= 1) {
        if (threadIdx.x < s) red[threadIdx.x] += red[threadIdx.x + s];
        __syncthreads();
    }
    if (threadIdx.x == 0) {
        atomicAdd(&g_acc, red[0]);
        __threadfence();
        unsigned done = atomicAdd(&g_cnt, 1u);
        if (done == gridDim.x - 1) {
            float total = atomicAdd(&g_acc, 0.0f);   // coherent L2 read
            out[0] = total / (float)N_TOTAL;
        }
    }
}

// ============================================================================
// launch
// ============================================================================
extern "C" void kernel_launch(void* const* d_in, const int* in_sizes, int n_in,
                              void* d_out, int out_size) {
    (void)in_sizes; (void)n_in; (void)out_size;
    const float* zi = (const float*)d_in[0];
    const float* zj = (const float*)d_in[1];
    float* out = (float*)d_out;

    normalize_kernel<<<N_TOTAL / 8, 256>>>(zi, zj);

    cudaFuncSetAttribute(gram_kernel,
                         cudaFuncAttributeMaxDynamicSharedMemorySize, SMEM_TOT);
    gram_kernel<<<GRID_GRAM, 256, SMEM_TOT>>>();

    finalize_kernel<<<N_TOTAL / 256, 256>>>(out);
}